// round 7
// baseline (speedup 1.0000x reference)
#include <cuda_runtime.h>
#include <math.h>

#define N_PTS 8192
#define M_PTS 2048
#define K_LAST 10
#define VARS 3

typedef unsigned long long u64;

// ---------------- packed f32x2 helpers (sm_100+) ----------------
__device__ __forceinline__ u64 pk2(float lo, float hi) {
    u64 r; asm("mov.b64 %0,{%1,%2};" : "=l"(r) : "f"(lo), "f"(hi)); return r;
}
__device__ __forceinline__ u64 dup2(float x) { return pk2(x, x); }
__device__ __forceinline__ void unpk2(u64 v, float& lo, float& hi) {
    asm("mov.b64 {%0,%1},%2;" : "=f"(lo), "=f"(hi) : "l"(v));
}
__device__ __forceinline__ u64 f2fma(u64 a, u64 b, u64 c) {
    u64 d; asm("fma.rn.f32x2 %0,%1,%2,%3;" : "=l"(d) : "l"(a), "l"(b), "l"(c)); return d;
}
__device__ __forceinline__ u64 f2mul(u64 a, u64 b) {
    u64 d; asm("mul.rn.f32x2 %0,%1,%2;" : "=l"(d) : "l"(a), "l"(b)); return d;
}
__device__ __forceinline__ u64 f2add(u64 a, u64 b) {
    u64 d; asm("add.rn.f32x2 %0,%1,%2;" : "=l"(d) : "l"(a), "l"(b)); return d;
}

// scalar exact GELU for proj kernel
__device__ __forceinline__ float gelu(float x) {
    return 0.5f * x * (1.0f + erff(x * 0.70710678118654752f));
}

// packed GELU via Abramowitz-Stegun 7.1.26 erf (abs err <= 1.5e-7), branchless
__device__ __forceinline__ u64 gelu2(u64 x) {
    u64 ax = x & 0x7FFFFFFF7FFFFFFFULL;
    u64 z  = f2mul(ax, dup2(0.70710678118654752f));
    u64 den = f2fma(z, dup2(0.3275911f), dup2(1.0f));
    float dl, dh, rl, rh;
    unpk2(den, dl, dh);
    asm("rcp.approx.f32 %0,%1;" : "=f"(rl) : "f"(dl));
    asm("rcp.approx.f32 %0,%1;" : "=f"(rh) : "f"(dh));
    u64 t = pk2(rl, rh);
    u64 z2 = f2mul(z, z);
    u64 m  = f2mul(z2, dup2(-1.4426950408889634f));
    float ml, mh, el, eh;
    unpk2(m, ml, mh);
    asm("ex2.approx.f32 %0,%1;" : "=f"(el) : "f"(ml));
    asm("ex2.approx.f32 %0,%1;" : "=f"(eh) : "f"(mh));
    u64 e = pk2(el, eh);
    u64 p = f2fma(t, dup2(1.061405429f), dup2(-1.453152027f));
    p = f2fma(p, t, dup2(1.421413741f));
    p = f2fma(p, t, dup2(-0.284496736f));
    p = f2fma(p, t, dup2(0.254829592f));
    p = f2mul(p, t);
    u64 np = p ^ 0x8000000080000000ULL;
    u64 u  = f2fma(np, e, dup2(1.0f));
    u64 E  = u | (x & 0x8000000080000000ULL);
    u64 h  = f2fma(E, dup2(0.5f), dup2(0.5f));
    return f2mul(x, h);
}

// ---- constant weight bank (one it-set at a time, swapped by memcpy) ----
// layout (float offsets): W0[36*80]@0, b0[80]@2880, W1[80*80]@2960,
//                         W2[80*32]@9360, b1[80]@11920, b2[32]@12000
#define CW0 0
#define CB0 2880
#define CW1 2960
#define CW2 9360
#define CB1 11920
#define CB2 12000
__constant__ float __align__(16) cW[12032];

// scratch
__device__ float g_f0[VARS * N_PTS * 32];
__device__ float g_acc[VARS * N_PTS * 32];
__device__ float g_A[VARS * N_PTS * 80];   // per-source-node layer1 partial
__device__ float g_D[N_PTS * 80];          // per-dest-node layer1 partial

// ---------------------------------------------------------------------------
// Projection MLP: per (var,point): 8 -> gelu 64 -> 32. One warp per (var,pt).
// ---------------------------------------------------------------------------
__global__ void proj_kernel(const float* __restrict__ inp,
                            const float* __restrict__ W0, const float* __restrict__ b0,
                            const float* __restrict__ W1, const float* __restrict__ b1,
                            float* __restrict__ f0) {
    __shared__ float hs[4][64];
    int warp = threadIdx.x >> 5, lane = threadIdx.x & 31;
    int pv = blockIdx.x * 4 + warp;
    if (pv >= VARS * N_PTS) return;
    int v = pv / N_PTS, n = pv - v * N_PTS;
    const float* x = inp + n * (VARS * 8) + v * 8;
    float xr[8];
#pragma unroll
    for (int i = 0; i < 8; i++) xr[i] = x[i];
    float a0 = b0[lane], a1 = b0[lane + 32];
#pragma unroll
    for (int i = 0; i < 8; i++) {
        a0 = fmaf(xr[i], W0[i * 64 + lane], a0);
        a1 = fmaf(xr[i], W0[i * 64 + lane + 32], a1);
    }
    hs[warp][lane]      = gelu(a0);
    hs[warp][lane + 32] = gelu(a1);
    __syncwarp();
    float acc = b1[lane];
#pragma unroll
    for (int h = 0; h < 64; h++) acc = fmaf(hs[warp][h], W1[h * 32 + lane], acc);
    f0[(size_t)pv * 32 + lane] = acc;
}

// ---------------------------------------------------------------------------
// pre_src: A[v][n][80] = b0 + W0row0*pos.x + W0row1*pos.y + sum_j f[j]*W0row(4+j)
// ---------------------------------------------------------------------------
__global__ void __launch_bounds__(128)
pre_src_kernel(const float* __restrict__ grid, const float* __restrict__ fsrc,
               float* __restrict__ Abuf) {
    int idx = blockIdx.x * 128 + threadIdx.x;
    if (idx >= VARS * N_PTS) return;
    int v = idx / N_PTS, n = idx - v * N_PTS;

    u64 acc[40];
#pragma unroll
    for (int q = 0; q < 20; q++) {
        ulonglong2 b = *(const ulonglong2*)(cW + CB0 + 4 * q);
        acc[2 * q] = b.x; acc[2 * q + 1] = b.y;
    }
    // position rows 0,1
    {
        u64 px = dup2(grid[2 * n]), py = dup2(grid[2 * n + 1]);
#pragma unroll
        for (int q = 0; q < 20; q++) {
            ulonglong2 w0 = *(const ulonglong2*)(cW + CW0 + 0 * 80 + 4 * q);
            ulonglong2 w1 = *(const ulonglong2*)(cW + CW0 + 1 * 80 + 4 * q);
            acc[2*q]   = f2fma(px, w0.x, acc[2*q]);
            acc[2*q+1] = f2fma(px, w0.y, acc[2*q+1]);
            acc[2*q]   = f2fma(py, w1.x, acc[2*q]);
            acc[2*q+1] = f2fma(py, w1.y, acc[2*q+1]);
        }
    }
    // f rows 4..35
    const float* fp = fsrc + (size_t)idx * 32;
#pragma unroll 4
    for (int j = 0; j < 32; j++) {
        u64 d = dup2(fp[j]);
        const float* wr = cW + CW0 + (4 + j) * 80;
#pragma unroll
        for (int q = 0; q < 20; q++) {
            ulonglong2 w = *(const ulonglong2*)(wr + 4 * q);
            acc[2*q]   = f2fma(d, w.x, acc[2*q]);
            acc[2*q+1] = f2fma(d, w.y, acc[2*q+1]);
        }
    }
    ulonglong2* dst = (ulonglong2*)(Abuf + (size_t)idx * 80);
#pragma unroll
    for (int q = 0; q < 20; q++) {
        ulonglong2 t; t.x = acc[2*q]; t.y = acc[2*q+1];
        dst[q] = t;
    }
}

// ---------------------------------------------------------------------------
// pre_dst: D[n][80] = W0row2*pos.x + W0row3*pos.y  (var-independent)
// ---------------------------------------------------------------------------
__global__ void __launch_bounds__(128)
pre_dst_kernel(const float* __restrict__ grid, float* __restrict__ Dbuf, int npts) {
    int n = blockIdx.x * 128 + threadIdx.x;
    if (n >= npts) return;
    u64 px = dup2(grid[2 * n]), py = dup2(grid[2 * n + 1]);
    ulonglong2* dst = (ulonglong2*)(Dbuf + (size_t)n * 80);
#pragma unroll
    for (int q = 0; q < 20; q++) {
        ulonglong2 w2 = *(const ulonglong2*)(cW + CW0 + 2 * 80 + 4 * q);
        ulonglong2 w3 = *(const ulonglong2*)(cW + CW0 + 3 * 80 + 4 * q);
        ulonglong2 t;
        t.x = f2fma(py, w3.x, f2mul(px, w2.x));
        t.y = f2fma(py, w3.y, f2mul(px, w2.y));
        dst[q] = t;
    }
}

// ---------------------------------------------------------------------------
// Edge kernel: h1 = gelu(A[jn] + D[seg]); 80 ->(W1,gelu) 80 ->(W2) 32.
// Weights via constant bank (uniform LDC), h via per-thread smem (stride 42
// u64, conflict-free), accumulators in registers. One edge per thread.
// ---------------------------------------------------------------------------
#define TPB 128

template <int MODE>
__global__ void __launch_bounds__(TPB, 4)
edge_kernel(const float* __restrict__ Abuf, const float* __restrict__ Dbuf,
            const int* __restrict__ idxA, const int* __restrict__ idxB,
            float* __restrict__ outbuf, int E) {
    __shared__ u64 hsh[TPB * 42];
    int tid = threadIdx.x;
    int v = blockIdx.y;
    int e = blockIdx.x * TPB + tid;
    bool valid = e < E;
    if (!valid) e = 0;
    int jn = idxA[e];
    int segd = (MODE == 0) ? idxB[e] : e / K_LAST;

    const ulonglong2* Ar = (const ulonglong2*)(Abuf + ((size_t)v * N_PTS + jn) * 80);
    const ulonglong2* Dr = (const ulonglong2*)(Dbuf + (size_t)segd * 80);
    ulonglong2* myh = (ulonglong2*)(hsh + tid * 42);

    // ---- layer 1 finish: add + gelu -> smem ----
#pragma unroll 5
    for (int q = 0; q < 20; q++) {
        ulonglong2 a = Ar[q], d = Dr[q];
        ulonglong2 g;
        g.x = gelu2(f2add(a.x, d.x));
        g.y = gelu2(f2add(a.y, d.y));
        myh[q] = g;
    }

    // ---- layer 2: 80 -> 80 ----
    u64 acc[40];
#pragma unroll
    for (int q = 0; q < 20; q++) {
        ulonglong2 b = *(const ulonglong2*)(cW + CB1 + 4 * q);
        acc[2*q] = b.x; acc[2*q+1] = b.y;
    }
#pragma unroll 1
    for (int kq = 0; kq < 20; kq++) {       // k = 4*kq .. 4*kq+3
        ulonglong2 hq = myh[kq];
        float h0, h1, h2, h3;
        unpk2(hq.x, h0, h1); unpk2(hq.y, h2, h3);
        u64 d0 = dup2(h0), d1 = dup2(h1), d2 = dup2(h2), d3 = dup2(h3);
        const float* wr = cW + CW1 + (4 * kq) * 80;
#pragma unroll
        for (int q = 0; q < 20; q++) {
            ulonglong2 w0 = *(const ulonglong2*)(wr + 4 * q);
            ulonglong2 w1 = *(const ulonglong2*)(wr + 80 + 4 * q);
            ulonglong2 w2 = *(const ulonglong2*)(wr + 160 + 4 * q);
            ulonglong2 w3 = *(const ulonglong2*)(wr + 240 + 4 * q);
            acc[2*q]   = f2fma(d0, w0.x, acc[2*q]);
            acc[2*q+1] = f2fma(d0, w0.y, acc[2*q+1]);
            acc[2*q]   = f2fma(d1, w1.x, acc[2*q]);
            acc[2*q+1] = f2fma(d1, w1.y, acc[2*q+1]);
            acc[2*q]   = f2fma(d2, w2.x, acc[2*q]);
            acc[2*q+1] = f2fma(d2, w2.y, acc[2*q+1]);
            acc[2*q]   = f2fma(d3, w3.x, acc[2*q]);
            acc[2*q+1] = f2fma(d3, w3.y, acc[2*q+1]);
        }
    }
    // gelu -> smem (h2)
#pragma unroll 5
    for (int q = 0; q < 20; q++) {
        ulonglong2 g;
        g.x = gelu2(acc[2*q]);
        g.y = gelu2(acc[2*q+1]);
        myh[q] = g;
    }

    // ---- layer 3: 80 -> 32 ----
    u64 out[16];
#pragma unroll
    for (int q = 0; q < 8; q++) {
        ulonglong2 b = *(const ulonglong2*)(cW + CB2 + 4 * q);
        out[2*q] = b.x; out[2*q+1] = b.y;
    }
#pragma unroll 1
    for (int kq = 0; kq < 20; kq++) {
        ulonglong2 hq = myh[kq];
        float h0, h1, h2, h3;
        unpk2(hq.x, h0, h1); unpk2(hq.y, h2, h3);
        u64 d0 = dup2(h0), d1 = dup2(h1), d2 = dup2(h2), d3 = dup2(h3);
        const float* wr = cW + CW2 + (4 * kq) * 32;
#pragma unroll
        for (int q = 0; q < 8; q++) {
            ulonglong2 w0 = *(const ulonglong2*)(wr + 4 * q);
            ulonglong2 w1 = *(const ulonglong2*)(wr + 32 + 4 * q);
            ulonglong2 w2 = *(const ulonglong2*)(wr + 64 + 4 * q);
            ulonglong2 w3 = *(const ulonglong2*)(wr + 96 + 4 * q);
            out[2*q]   = f2fma(d0, w0.x, out[2*q]);
            out[2*q+1] = f2fma(d0, w0.y, out[2*q+1]);
            out[2*q]   = f2fma(d1, w1.x, out[2*q]);
            out[2*q+1] = f2fma(d1, w1.y, out[2*q+1]);
            out[2*q]   = f2fma(d2, w2.x, out[2*q]);
            out[2*q+1] = f2fma(d2, w2.y, out[2*q+1]);
            out[2*q]   = f2fma(d3, w3.x, out[2*q]);
            out[2*q+1] = f2fma(d3, w3.y, out[2*q+1]);
        }
    }

    // ---- scatter ----
    if (valid) {
        float* dst; float scale;
        if (MODE == 0) { dst = outbuf + ((size_t)v * N_PTS + segd) * 32; scale = 1.0f; }
        else           { dst = outbuf + (size_t)segd * (VARS * 32) + v * 32; scale = 0.1f; }
#pragma unroll
        for (int q = 0; q < 16; q++) {
            float a, b; unpk2(out[q], a, b);
            atomicAdd(dst + 2 * q,     a * scale);
            atomicAdd(dst + 2 * q + 1, b * scale);
        }
    }
}

// f1 = segment_sum * inv_count + f0 (in place into f0)
__global__ void f1_kernel(float* __restrict__ f0, const float* __restrict__ acc,
                          const int* __restrict__ counts) {
    int idx = blockIdx.x * 256 + threadIdx.x;
    if (idx >= VARS * N_PTS * 32) return;
    int n = (idx >> 5) % N_PTS;
    int c = counts[n];
    float inv = 1.0f / (float)(c > 1 ? c : 1);
    f0[idx] = fmaf(acc[idx], inv, f0[idx]);
}

static void copy_weight_set(const float* W0, const float* b0, const float* W1,
                            const float* b1, const float* W2, const float* b2) {
    cudaMemcpyToSymbolAsync(cW, W0, 2880 * 4, CW0 * 4, cudaMemcpyDeviceToDevice);
    cudaMemcpyToSymbolAsync(cW, b0,   80 * 4, CB0 * 4, cudaMemcpyDeviceToDevice);
    cudaMemcpyToSymbolAsync(cW, W1, 6400 * 4, CW1 * 4, cudaMemcpyDeviceToDevice);
    cudaMemcpyToSymbolAsync(cW, W2, 2560 * 4, CW2 * 4, cudaMemcpyDeviceToDevice);
    cudaMemcpyToSymbolAsync(cW, b1,   80 * 4, CB1 * 4, cudaMemcpyDeviceToDevice);
    cudaMemcpyToSymbolAsync(cW, b2,   32 * 4, CB2 * 4, cudaMemcpyDeviceToDevice);
}

extern "C" void kernel_launch(void* const* d_in, const int* in_sizes, int n_in,
                              void* d_out, int out_size) {
    const float* inp   = (const float*)d_in[0];
    const float* gin   = (const float*)d_in[1];
    const float* gout  = (const float*)d_in[2];
    const float* pW0   = (const float*)d_in[3];
    const float* pb0   = (const float*)d_in[4];
    const float* pW1   = (const float*)d_in[5];
    const float* pb1   = (const float*)d_in[6];
    const float* i0W0  = (const float*)d_in[7];
    const float* i0b0  = (const float*)d_in[8];
    const float* i0W1  = (const float*)d_in[9];
    const float* i0b1  = (const float*)d_in[10];
    const float* i0W2  = (const float*)d_in[11];
    const float* i0b2  = (const float*)d_in[12];
    const float* i1W0  = (const float*)d_in[13];
    const float* i1b0  = (const float*)d_in[14];
    const float* i1W1  = (const float*)d_in[15];
    const float* i1b1  = (const float*)d_in[16];
    const float* i1W2  = (const float*)d_in[17];
    const float* i1b2  = (const float*)d_in[18];
    const int* nbr_index  = (const int*)d_in[19];
    const int* nbr_seg    = (const int*)d_in[20];
    const int* nbr_counts = (const int*)d_in[21];
    const int* nbr_last   = (const int*)d_in[22];
    int E = in_sizes[19];

    float *f0, *acc, *Abuf, *Dbuf;
    cudaGetSymbolAddress((void**)&f0,   g_f0);
    cudaGetSymbolAddress((void**)&acc,  g_acc);
    cudaGetSymbolAddress((void**)&Abuf, g_A);
    cudaGetSymbolAddress((void**)&Dbuf, g_D);

    cudaMemsetAsync(acc, 0, sizeof(float) * VARS * N_PTS * 32);
    cudaMemsetAsync(d_out, 0, sizeof(float) * (size_t)out_size);

    // phase 0: it0 weight set
    copy_weight_set(i0W0, i0b0, i0W1, i0b1, i0W2, i0b2);

    proj_kernel<<<(VARS * N_PTS + 3) / 4, 128>>>(inp, pW0, pb0, pW1, pb1, f0);

    pre_dst_kernel<<<(N_PTS + 127) / 128, 128>>>(gin, Dbuf, N_PTS);
    pre_src_kernel<<<(VARS * N_PTS + 127) / 128, 128>>>(gin, f0, Abuf);

    dim3 g1((unsigned)((E + TPB - 1) / TPB), VARS);
    edge_kernel<0><<<g1, TPB>>>(Abuf, Dbuf, nbr_index, nbr_seg, acc, E);

    f1_kernel<<<(VARS * N_PTS * 32 + 255) / 256, 256>>>(f0, acc, nbr_counts);

    // phase 1: it1 weight set
    copy_weight_set(i1W0, i1b0, i1W1, i1b1, i1W2, i1b2);

    pre_dst_kernel<<<(M_PTS + 127) / 128, 128>>>(gout, Dbuf, M_PTS);
    pre_src_kernel<<<(VARS * N_PTS + 127) / 128, 128>>>(gin, f0, Abuf);

    int E2 = M_PTS * K_LAST;
    dim3 g2((unsigned)((E2 + TPB - 1) / TPB), VARS);
    edge_kernel<1><<<g2, TPB>>>(Abuf, Dbuf, nbr_last, nullptr, (float*)d_out, E2);
}

// round 9
// speedup vs baseline: 3.9084x; 3.9084x over previous
#include <cuda_runtime.h>
#include <cuda_bf16.h>
#include <math.h>
#include <stdint.h>

#define N_PTS 8192
#define M_PTS 2048
#define K_LAST 10
#define VARS 3

typedef unsigned long long u64;

// ---------------- packed f32x2 helpers ----------------
__device__ __forceinline__ u64 pk2(float lo, float hi) {
    u64 r; asm("mov.b64 %0,{%1,%2};" : "=l"(r) : "f"(lo), "f"(hi)); return r;
}
__device__ __forceinline__ u64 dup2(float x) { return pk2(x, x); }
__device__ __forceinline__ void unpk2(u64 v, float& lo, float& hi) {
    asm("mov.b64 {%0,%1},%2;" : "=f"(lo), "=f"(hi) : "l"(v));
}
__device__ __forceinline__ u64 f2fma(u64 a, u64 b, u64 c) {
    u64 d; asm("fma.rn.f32x2 %0,%1,%2,%3;" : "=l"(d) : "l"(a), "l"(b), "l"(c)); return d;
}
__device__ __forceinline__ u64 f2mul(u64 a, u64 b) {
    u64 d; asm("mul.rn.f32x2 %0,%1,%2;" : "=l"(d) : "l"(a), "l"(b)); return d;
}

__device__ __forceinline__ float gelu(float x) {
    return 0.5f * x * (1.0f + erff(x * 0.70710678118654752f));
}

// packed GELU (A&S 7.1.26 erf, abs err <= 1.5e-7)
__device__ __forceinline__ u64 gelu2(u64 x) {
    u64 ax = x & 0x7FFFFFFF7FFFFFFFULL;
    u64 z  = f2mul(ax, dup2(0.70710678118654752f));
    u64 den = f2fma(z, dup2(0.3275911f), dup2(1.0f));
    float dl, dh, rl, rh;
    unpk2(den, dl, dh);
    asm("rcp.approx.f32 %0,%1;" : "=f"(rl) : "f"(dl));
    asm("rcp.approx.f32 %0,%1;" : "=f"(rh) : "f"(dh));
    u64 t = pk2(rl, rh);
    u64 z2 = f2mul(z, z);
    u64 m  = f2mul(z2, dup2(-1.4426950408889634f));
    float ml, mh, el, eh;
    unpk2(m, ml, mh);
    asm("ex2.approx.f32 %0,%1;" : "=f"(el) : "f"(ml));
    asm("ex2.approx.f32 %0,%1;" : "=f"(eh) : "f"(mh));
    u64 e = pk2(el, eh);
    u64 p = f2fma(t, dup2(1.061405429f), dup2(-1.453152027f));
    p = f2fma(p, t, dup2(1.421413741f));
    p = f2fma(p, t, dup2(-0.284496736f));
    p = f2fma(p, t, dup2(0.254829592f));
    p = f2mul(p, t);
    u64 np = p ^ 0x8000000080000000ULL;
    u64 u  = f2fma(np, e, dup2(1.0f));
    u64 E  = u | (x & 0x8000000080000000ULL);
    u64 h  = f2fma(E, dup2(0.5f), dup2(0.5f));
    return f2mul(x, h);
}

// pack two floats to bf16x2 (a -> low 16 bits, b -> high)
__device__ __forceinline__ uint32_t pack_bf16(float a, float b) {
    uint32_t r; asm("cvt.rn.bf16x2.f32 %0, %1, %2;" : "=r"(r) : "f"(b), "f"(a));
    return r;
}
// split f32 pair into (hi bf16x2, lo bf16x2)
__device__ __forceinline__ void split_pack(float f0, float f1, uint32_t& hi, uint32_t& lo) {
    hi = pack_bf16(f0, f1);
    float h0 = __uint_as_float(hi << 16);
    float h1 = __uint_as_float(hi & 0xFFFF0000u);
    lo = pack_bf16(f0 - h0, f1 - h1);
}

// m16n8k16 bf16 MMA, D (f32) accumulate in place
__device__ __forceinline__ void mma16816(float* d, const uint32_t* a, uint32_t b0, uint32_t b1) {
    asm volatile(
        "mma.sync.aligned.m16n8k16.row.col.f32.bf16.bf16.f32 "
        "{%0,%1,%2,%3}, {%4,%5,%6,%7}, {%8,%9}, {%0,%1,%2,%3};"
        : "+f"(d[0]), "+f"(d[1]), "+f"(d[2]), "+f"(d[3])
        : "r"(a[0]), "r"(a[1]), "r"(a[2]), "r"(a[3]), "r"(b0), "r"(b1));
}

// ---------------- scratch ----------------
__device__ float g_f0[VARS * N_PTS * 32];
__device__ float g_acc[VARS * N_PTS * 32];
__device__ uint8_t g_blob[2][51200];
// blob byte offsets (fragment-major weights, hi/lo):
#define BL1H 0
#define BL1L 7680
#define BL2H 15360
#define BL2L 28160
#define BL3H 40960
#define BL3L 46080
#define BLOB_BYTES 51200

// ---------------- weight prep: per-lane MMA B fragments, split bf16 ----------------
// W is [Kreal x N] row-major. Fragment set (kt,nt): lane holds n = nt*8+lane/4,
// k0 = kt*16+2*(lane%4): reg0={W[k0][n],W[k0+1][n]}, reg1={W[k0+8][n],W[k0+9][n]}.
__global__ void prep_frag_kernel(const float* __restrict__ W, int Kreal, int KT, int NT, int N,
                                 uint8_t* __restrict__ dhi, uint8_t* __restrict__ dlo) {
    int idx = blockIdx.x * 256 + threadIdx.x;
    if (idx >= KT * NT * 32) return;
    int lane = idx & 31, set = idx >> 5;
    int kt = set / NT, nt = set - kt * NT;
    int n = nt * 8 + (lane >> 2);
    int k0 = kt * 16 + 2 * (lane & 3);
    float v[4];
#pragma unroll
    for (int j = 0; j < 4; j++) {
        int k = k0 + (j >> 1) * 8 + (j & 1);
        v[j] = (k < Kreal) ? W[k * N + n] : 0.f;
    }
    uint32_t h0, l0, h1, l1;
    split_pack(v[0], v[1], h0, l0);
    split_pack(v[2], v[3], h1, l1);
    *(u64*)(dhi + (size_t)set * 256 + lane * 8) = (u64)h0 | ((u64)h1 << 32);
    *(u64*)(dlo + (size_t)set * 256 + lane * 8) = (u64)l0 | ((u64)l1 << 32);
}

// ---------------- projection MLP ----------------
__global__ void proj_kernel(const float* __restrict__ inp,
                            const float* __restrict__ W0, const float* __restrict__ b0,
                            const float* __restrict__ W1, const float* __restrict__ b1,
                            float* __restrict__ f0) {
    __shared__ float hs[4][64];
    int warp = threadIdx.x >> 5, lane = threadIdx.x & 31;
    int pv = blockIdx.x * 4 + warp;
    if (pv >= VARS * N_PTS) return;
    int v = pv / N_PTS, n = pv - v * N_PTS;
    const float* x = inp + n * (VARS * 8) + v * 8;
    float xr[8];
#pragma unroll
    for (int i = 0; i < 8; i++) xr[i] = x[i];
    float a0 = b0[lane], a1 = b0[lane + 32];
#pragma unroll
    for (int i = 0; i < 8; i++) {
        a0 = fmaf(xr[i], W0[i * 64 + lane], a0);
        a1 = fmaf(xr[i], W0[i * 64 + lane + 32], a1);
    }
    hs[warp][lane]      = gelu(a0);
    hs[warp][lane + 32] = gelu(a1);
    __syncwarp();
    float acc = b1[lane];
#pragma unroll
    for (int h = 0; h < 64; h++) acc = fmaf(hs[warp][h], W1[h * 32 + lane], acc);
    f0[(size_t)pv * 32 + lane] = acc;
}

// ---------------- HMMA edge MLP ----------------
// Block: 128 threads = 4 warps; each warp processes 2 tiles of 16 edges.
// smem: weight-fragment blob 51200B, biases, per-warp x stage [16][48] f32, seg[16].
#define TPB 128
#define SM_BS0   51200
#define SM_BS1   51520
#define SM_BS2   51840
#define SM_XST   51968          // + warp*3072
#define SM_SEG   64256          // + warp*64
#define SMEM_BYTES 64512

template <int MODE>
__global__ void __launch_bounds__(TPB, 3)
edge_mma_kernel(const uint8_t* __restrict__ blob,
                const float* __restrict__ b0g, const float* __restrict__ b1g,
                const float* __restrict__ b2g,
                const float* __restrict__ grid_in, const float* __restrict__ grid_out,
                const float* __restrict__ fsrc,
                const int* __restrict__ idxA, const int* __restrict__ idxB,
                float* __restrict__ outbuf, int E) {
    extern __shared__ __align__(16) uint8_t sm[];
    int tid = threadIdx.x;
    int warp = tid >> 5, lane = tid & 31;
    int g = lane >> 2;          // row group 0..7
    int t = lane & 3;           // thread-in-group
    int v = blockIdx.y;

    // stage blob + biases
    {
        const uint4* src = (const uint4*)blob;
        uint4* dst = (uint4*)sm;
        for (int i = tid; i < BLOB_BYTES / 16; i += TPB) dst[i] = src[i];
        float* bs0 = (float*)(sm + SM_BS0);
        float* bs1 = (float*)(sm + SM_BS1);
        float* bs2 = (float*)(sm + SM_BS2);
        if (tid < 80) { bs0[tid] = b0g[tid]; bs1[tid] = b1g[tid]; }
        if (tid < 32) bs2[tid] = b2g[tid];
    }
    __syncthreads();

    float* xst = (float*)(sm + SM_XST + warp * 3072);
    int*   seg_sh = (int*)(sm + SM_SEG + warp * 64);
    const float* bs0 = (const float*)(sm + SM_BS0);
    const float* bs1 = (const float*)(sm + SM_BS1);
    const float* bs2 = (const float*)(sm + SM_BS2);

#pragma unroll 1
    for (int mt = 0; mt < 2; mt++) {
        int tileBase = blockIdx.x * 128 + warp * 32 + mt * 16;

        // ---- gather: 2 lanes per edge ----
        {
            int el = lane & 15, half = lane >> 4;
            int e = tileBase + el;
            bool gv = e < E;
            int ee = gv ? e : 0;
            int jn = idxA[ee];
            int sg = (MODE == 0) ? idxB[ee] : ee / K_LAST;
            float* xrow = xst + el * 48;
            if (half == 0) {
                seg_sh[el] = gv ? sg : -1;
                float p0 = 0, p1 = 0, p2 = 0, p3 = 0;
                if (gv) {
                    p0 = grid_in[2 * jn]; p1 = grid_in[2 * jn + 1];
                    if (MODE == 0) { p2 = grid_in[2 * sg];  p3 = grid_in[2 * sg + 1]; }
                    else           { p2 = grid_out[2 * sg]; p3 = grid_out[2 * sg + 1]; }
                }
                xrow[0] = p0; xrow[1] = p1; xrow[2] = p2; xrow[3] = p3;
            }
            const float4* fp = (const float4*)(fsrc + ((size_t)v * N_PTS + jn) * 32 + half * 16);
            float4* xd = (float4*)(xrow + 4 + 16 * half);
            xd[0] = fp[0]; xd[1] = fp[1]; xd[2] = fp[2]; xd[3] = fp[3];
            if (half == 1) {
                float4 z = make_float4(0.f, 0.f, 0.f, 0.f);
                float4* zz = (float4*)(xrow + 36);
                zz[0] = z; zz[1] = z; zz[2] = z;
            }
        }
        __syncwarp();

        // ---- A1 fragments from x stage (3 k-tiles of 16) ----
        uint32_t a1h[3][4], a1l[3][4];
#pragma unroll
        for (int kt = 0; kt < 3; kt++) {
#pragma unroll
            for (int rr = 0; rr < 4; rr++) {
                int row = g + (rr & 1) * 8;
                int col = 16 * kt + 2 * t + (rr >> 1) * 8;
                u64 pv_ = *(const u64*)(xst + row * 48 + col);
                float f0, f1; unpk2(pv_, f0, f1);
                split_pack(f0, f1, a1h[kt][rr], a1l[kt][rr]);
            }
        }

        // ---- layer 1: K=48, N=80 (10 n-tiles) ----
        float d1[10][4];
#pragma unroll
        for (int nt = 0; nt < 10; nt++) {
            float* d = d1[nt];
            d[0] = 0.f; d[1] = 0.f; d[2] = 0.f; d[3] = 0.f;
#pragma unroll
            for (int kt = 0; kt < 3; kt++) {
                int set = kt * 10 + nt;
                u64 bh = *(const u64*)(sm + BL1H + (size_t)set * 256 + lane * 8);
                u64 bl = *(const u64*)(sm + BL1L + (size_t)set * 256 + lane * 8);
                uint32_t bh0 = (uint32_t)bh, bh1 = (uint32_t)(bh >> 32);
                uint32_t bl0 = (uint32_t)bl, bl1 = (uint32_t)(bl >> 32);
                mma16816(d, a1h[kt], bh0, bh1);
                mma16816(d, a1h[kt], bl0, bl1);
                mma16816(d, a1l[kt], bh0, bh1);
            }
        }

        // ---- epilogue 1: bias + gelu + split -> A2 fragments ----
        uint32_t a2h[5][4], a2l[5][4];
#pragma unroll
        for (int m = 0; m < 5; m++) {
            int j0 = 2 * m, j1 = 2 * m + 1;
            float bb0, bb1, bb2, bb3;
            unpk2(*(const u64*)(bs0 + 8 * j0 + 2 * t), bb0, bb1);
            unpk2(*(const u64*)(bs0 + 8 * j1 + 2 * t), bb2, bb3);
            float q0, q1;
            unpk2(gelu2(pk2(d1[j0][0] + bb0, d1[j0][1] + bb1)), q0, q1);
            split_pack(q0, q1, a2h[m][0], a2l[m][0]);
            unpk2(gelu2(pk2(d1[j0][2] + bb0, d1[j0][3] + bb1)), q0, q1);
            split_pack(q0, q1, a2h[m][1], a2l[m][1]);
            unpk2(gelu2(pk2(d1[j1][0] + bb2, d1[j1][1] + bb3)), q0, q1);
            split_pack(q0, q1, a2h[m][2], a2l[m][2]);
            unpk2(gelu2(pk2(d1[j1][2] + bb2, d1[j1][3] + bb3)), q0, q1);
            split_pack(q0, q1, a2h[m][3], a2l[m][3]);
        }

        // ---- layer 2: K=80, N=80 ----
        float d2[10][4];
#pragma unroll
        for (int nt = 0; nt < 10; nt++) {
            float* d = d2[nt];
            d[0] = 0.f; d[1] = 0.f; d[2] = 0.f; d[3] = 0.f;
#pragma unroll
            for (int kt = 0; kt < 5; kt++) {
                int set = kt * 10 + nt;
                u64 bh = *(const u64*)(sm + BL2H + (size_t)set * 256 + lane * 8);
                u64 bl = *(const u64*)(sm + BL2L + (size_t)set * 256 + lane * 8);
                uint32_t bh0 = (uint32_t)bh, bh1 = (uint32_t)(bh >> 32);
                uint32_t bl0 = (uint32_t)bl, bl1 = (uint32_t)(bl >> 32);
                mma16816(d, a2h[kt], bh0, bh1);
                mma16816(d, a2h[kt], bl0, bl1);
                mma16816(d, a2l[kt], bh0, bh1);
            }
        }

        // ---- epilogue 2 -> A3 fragments ----
        uint32_t a3h[5][4], a3l[5][4];
#pragma unroll
        for (int m = 0; m < 5; m++) {
            int j0 = 2 * m, j1 = 2 * m + 1;
            float bb0, bb1, bb2, bb3;
            unpk2(*(const u64*)(bs1 + 8 * j0 + 2 * t), bb0, bb1);
            unpk2(*(const u64*)(bs1 + 8 * j1 + 2 * t), bb2, bb3);
            float q0, q1;
            unpk2(gelu2(pk2(d2[j0][0] + bb0, d2[j0][1] + bb1)), q0, q1);
            split_pack(q0, q1, a3h[m][0], a3l[m][0]);
            unpk2(gelu2(pk2(d2[j0][2] + bb0, d2[j0][3] + bb1)), q0, q1);
            split_pack(q0, q1, a3h[m][1], a3l[m][1]);
            unpk2(gelu2(pk2(d2[j1][0] + bb2, d2[j1][1] + bb3)), q0, q1);
            split_pack(q0, q1, a3h[m][2], a3l[m][2]);
            unpk2(gelu2(pk2(d2[j1][2] + bb2, d2[j1][3] + bb3)), q0, q1);
            split_pack(q0, q1, a3h[m][3], a3l[m][3]);
        }

        // ---- layer 3: K=80, N=32 (4 n-tiles) ----
        float d3[4][4];
#pragma unroll
        for (int nt = 0; nt < 4; nt++) {
            float* d = d3[nt];
            d[0] = 0.f; d[1] = 0.f; d[2] = 0.f; d[3] = 0.f;
#pragma unroll
            for (int kt = 0; kt < 5; kt++) {
                int set = kt * 4 + nt;
                u64 bh = *(const u64*)(sm + BL3H + (size_t)set * 256 + lane * 8);
                u64 bl = *(const u64*)(sm + BL3L + (size_t)set * 256 + lane * 8);
                uint32_t bh0 = (uint32_t)bh, bh1 = (uint32_t)(bh >> 32);
                uint32_t bl0 = (uint32_t)bl, bl1 = (uint32_t)(bl >> 32);
                mma16816(d, a3h[kt], bh0, bh1);
                mma16816(d, a3h[kt], bl0, bl1);
                mma16816(d, a3l[kt], bh0, bh1);
            }
        }

        // ---- epilogue 3: bias + scatter (rows g and g+8) ----
        {
            int sg0 = seg_sh[g], sg1 = seg_sh[g + 8];
            float scale = (MODE == 0) ? 1.0f : 0.1f;
            float* dst0 = nullptr; float* dst1 = nullptr;
            if (MODE == 0) {
                if (sg0 >= 0) dst0 = outbuf + ((size_t)v * N_PTS + sg0) * 32;
                if (sg1 >= 0) dst1 = outbuf + ((size_t)v * N_PTS + sg1) * 32;
            } else {
                if (sg0 >= 0) dst0 = outbuf + (size_t)sg0 * (VARS * 32) + v * 32;
                if (sg1 >= 0) dst1 = outbuf + (size_t)sg1 * (VARS * 32) + v * 32;
            }
#pragma unroll
            for (int nt = 0; nt < 4; nt++) {
                float bb0, bb1;
                unpk2(*(const u64*)(bs2 + 8 * nt + 2 * t), bb0, bb1);
                int c0 = 8 * nt + 2 * t;
                if (dst0) {
                    atomicAdd(dst0 + c0,     (d3[nt][0] + bb0) * scale);
                    atomicAdd(dst0 + c0 + 1, (d3[nt][1] + bb1) * scale);
                }
                if (dst1) {
                    atomicAdd(dst1 + c0,     (d3[nt][2] + bb0) * scale);
                    atomicAdd(dst1 + c0 + 1, (d3[nt][3] + bb1) * scale);
                }
            }
        }
        __syncwarp();
    }
}

// f1 = segment_sum * inv_count + f0 (in place)
__global__ void f1_kernel(float* __restrict__ f0, const float* __restrict__ acc,
                          const int* __restrict__ counts) {
    int idx = blockIdx.x * 256 + threadIdx.x;
    if (idx >= VARS * N_PTS * 32) return;
    int n = (idx >> 5) % N_PTS;
    int c = counts[n];
    float inv = 1.0f / (float)(c > 1 ? c : 1);
    f0[idx] = fmaf(acc[idx], inv, f0[idx]);
}

extern "C" void kernel_launch(void* const* d_in, const int* in_sizes, int n_in,
                              void* d_out, int out_size) {
    const float* inp   = (const float*)d_in[0];
    const float* gin   = (const float*)d_in[1];
    const float* gout  = (const float*)d_in[2];
    const float* pW0   = (const float*)d_in[3];
    const float* pb0   = (const float*)d_in[4];
    const float* pW1   = (const float*)d_in[5];
    const float* pb1   = (const float*)d_in[6];
    const float* i0W0  = (const float*)d_in[7];
    const float* i0b0  = (const float*)d_in[8];
    const float* i0W1  = (const float*)d_in[9];
    const float* i0b1  = (const float*)d_in[10];
    const float* i0W2  = (const float*)d_in[11];
    const float* i0b2  = (const float*)d_in[12];
    const float* i1W0  = (const float*)d_in[13];
    const float* i1b0  = (const float*)d_in[14];
    const float* i1W1  = (const float*)d_in[15];
    const float* i1b1  = (const float*)d_in[16];
    const float* i1W2  = (const float*)d_in[17];
    const float* i1b2  = (const float*)d_in[18];
    const int* nbr_index  = (const int*)d_in[19];
    const int* nbr_seg    = (const int*)d_in[20];
    const int* nbr_counts = (const int*)d_in[21];
    const int* nbr_last   = (const int*)d_in[22];
    int E = in_sizes[19];

    float *f0, *acc;
    uint8_t* blob;
    cudaGetSymbolAddress((void**)&f0,   g_f0);
    cudaGetSymbolAddress((void**)&acc,  g_acc);
    cudaGetSymbolAddress((void**)&blob, g_blob);
    uint8_t* blob0 = blob;
    uint8_t* blob1 = blob + BLOB_BYTES;

    cudaMemsetAsync(acc, 0, sizeof(float) * VARS * N_PTS * 32);
    cudaMemsetAsync(d_out, 0, sizeof(float) * (size_t)out_size);

    // fragment prep: (W, Kreal, KT, NT, N, hi, lo)
    prep_frag_kernel<<<(30 * 32 + 255) / 256, 256>>>(i0W0, 36, 3, 10, 80, blob0 + BL1H, blob0 + BL1L);
    prep_frag_kernel<<<(50 * 32 + 255) / 256, 256>>>(i0W1, 80, 5, 10, 80, blob0 + BL2H, blob0 + BL2L);
    prep_frag_kernel<<<(20 * 32 + 255) / 256, 256>>>(i0W2, 80, 5, 4, 32, blob0 + BL3H, blob0 + BL3L);
    prep_frag_kernel<<<(30 * 32 + 255) / 256, 256>>>(i1W0, 36, 3, 10, 80, blob1 + BL1H, blob1 + BL1L);
    prep_frag_kernel<<<(50 * 32 + 255) / 256, 256>>>(i1W1, 80, 5, 10, 80, blob1 + BL2H, blob1 + BL2L);
    prep_frag_kernel<<<(20 * 32 + 255) / 256, 256>>>(i1W2, 80, 5, 4, 32, blob1 + BL3H, blob1 + BL3L);

    proj_kernel<<<(VARS * N_PTS + 3) / 4, 128>>>(inp, pW0, pb0, pW1, pb1, f0);

    cudaFuncSetAttribute(edge_mma_kernel<0>, cudaFuncAttributeMaxDynamicSharedMemorySize, SMEM_BYTES);
    cudaFuncSetAttribute(edge_mma_kernel<1>, cudaFuncAttributeMaxDynamicSharedMemorySize, SMEM_BYTES);

    dim3 g1((unsigned)((E + 127) / 128), VARS);
    edge_mma_kernel<0><<<g1, TPB, SMEM_BYTES>>>(blob0, i0b0, i0b1, i0b2,
                                                gin, nullptr, f0, nbr_index, nbr_seg, acc, E);

    f1_kernel<<<(VARS * N_PTS * 32 + 255) / 256, 256>>>(f0, acc, nbr_counts);

    int E2 = M_PTS * K_LAST;
    dim3 g2((unsigned)((E2 + 127) / 128), VARS);
    edge_mma_kernel<1><<<g2, TPB, SMEM_BYTES>>>(blob1, i1b0, i1b1, i1b2,
                                                gin, gout, f0, nbr_last, nullptr, (float*)d_out, E2);
}